// round 10
// baseline (speedup 1.0000x reference)
#include <cuda_runtime.h>

#define NEGV (-1.0e12f)

// Scratch (allocation-free rule: __device__ globals)
__device__ float g_proj[512u * 32u * 256u];          // 16 MB: proj[(d*32+b)*256 + e]
__device__ float g_scores[16384ull * 2048ull];       // 134 MB fallback if out lacks weights

// ---------------------------------------------------------------------------
// Generic NN GEMM: C[m,n] = sum_k A[m*lda+k] * B[k*ldb+n], 128x128 tile, BK=8,
// 8x8 per thread, 256 threads, double-buffered smem. All dims divide tiles.
// Per-z (batch) pointer offsets via sAz/sBz/sCz.
// ---------------------------------------------------------------------------
__global__ __launch_bounds__(256, 2)
void gemm_nn_kernel(const float* __restrict__ A, long long sAz, int lda,
                    const float* __restrict__ B, long long sBz, int ldb,
                    float* __restrict__ C, long long sCz, int ldc,
                    int K)
{
    A += (long long)blockIdx.z * sAz;
    B += (long long)blockIdx.z * sBz;
    C += (long long)blockIdx.z * sCz;
    const int bm = blockIdx.y * 128;
    const int bn = blockIdx.x * 128;

    __shared__ float As[2][8][128];
    __shared__ float Bs[2][8][128];

    const int tid = threadIdx.x;
    const int a_row = tid >> 1;          // 0..127
    const int a_k   = (tid & 1) * 4;     // 0 or 4
    const int b_k   = tid >> 5;          // 0..7
    const int b_n   = (tid & 31) * 4;    // 0..124

    const float* Ap = A + (long long)(bm + a_row) * lda + a_k;
    const float* Bp = B + (long long)b_k * ldb + bn + b_n;

    float4 ra = *(const float4*)Ap;
    float4 rb = *(const float4*)Bp;
    As[0][a_k + 0][a_row] = ra.x;
    As[0][a_k + 1][a_row] = ra.y;
    As[0][a_k + 2][a_row] = ra.z;
    As[0][a_k + 3][a_row] = ra.w;
    *(float4*)&Bs[0][b_k][b_n] = rb;
    __syncthreads();

    const int tx = tid & 15;
    const int ty = tid >> 4;

    float acc[8][8];
#pragma unroll
    for (int i = 0; i < 8; ++i)
#pragma unroll
        for (int j = 0; j < 8; ++j) acc[i][j] = 0.0f;

    const int KT = K >> 3;
    int cur = 0;
    for (int kt = 0; kt < KT; ++kt) {
        if (kt + 1 < KT) {
            ra = *(const float4*)(Ap + (long long)(kt + 1) * 8);
            rb = *(const float4*)(Bp + (long long)(kt + 1) * 8 * ldb);
        }
#pragma unroll
        for (int k = 0; k < 8; ++k) {
            float a[8], b[8];
            *(float4*)&a[0] = *(const float4*)&As[cur][k][ty * 8];
            *(float4*)&a[4] = *(const float4*)&As[cur][k][ty * 8 + 4];
            *(float4*)&b[0] = *(const float4*)&Bs[cur][k][tx * 8];
            *(float4*)&b[4] = *(const float4*)&Bs[cur][k][tx * 8 + 4];
#pragma unroll
            for (int i = 0; i < 8; ++i)
#pragma unroll
                for (int j = 0; j < 8; ++j)
                    acc[i][j] = fmaf(a[i], b[j], acc[i][j]);
        }
        if (kt + 1 < KT) {
            const int nx = cur ^ 1;
            As[nx][a_k + 0][a_row] = ra.x;
            As[nx][a_k + 1][a_row] = ra.y;
            As[nx][a_k + 2][a_row] = ra.z;
            As[nx][a_k + 3][a_row] = ra.w;
            *(float4*)&Bs[nx][b_k][b_n] = rb;
        }
        __syncthreads();
        cur ^= 1;
    }

#pragma unroll
    for (int i = 0; i < 8; ++i) {
        float* Cp = C + (long long)(bm + ty * 8 + i) * ldc + bn + tx * 8;
        *(float4*)Cp       = make_float4(acc[i][0], acc[i][1], acc[i][2], acc[i][3]);
        *(float4*)(Cp + 4) = make_float4(acc[i][4], acc[i][5], acc[i][6], acc[i][7]);
    }
}

// ---------------------------------------------------------------------------
// NT GEMM with mask epilogue: C[m,n] = sum_k A[m*lda+k] * B[n*ldb+k]
// Mask: element for column n is Mk[blockIdx.z + n*mStride]; 0 -> NEGV.
// ---------------------------------------------------------------------------
__global__ __launch_bounds__(256, 2)
void gemm_nt_mask_kernel(const float* __restrict__ A, long long sAz, int lda,
                         const float* __restrict__ B, long long sBz, int ldb,
                         float* __restrict__ C, long long sCz, int ldc,
                         const int* __restrict__ Mk, int mStride,
                         int K)
{
    A += (long long)blockIdx.z * sAz;
    B += (long long)blockIdx.z * sBz;
    C += (long long)blockIdx.z * sCz;
    const int* mp = Mk + blockIdx.z;
    const int bm = blockIdx.y * 128;
    const int bn = blockIdx.x * 128;

    __shared__ float As[2][8][128];
    __shared__ float Bs[2][8][128];

    const int tid = threadIdx.x;
    const int a_row = tid >> 1;
    const int a_k   = (tid & 1) * 4;
    const int b_row = tid >> 1;
    const int b_k   = (tid & 1) * 4;

    const float* Ap = A + (long long)(bm + a_row) * lda + a_k;
    const float* Bp = B + (long long)(bn + b_row) * ldb + b_k;

    float4 ra = *(const float4*)Ap;
    float4 rb = *(const float4*)Bp;
    As[0][a_k + 0][a_row] = ra.x;
    As[0][a_k + 1][a_row] = ra.y;
    As[0][a_k + 2][a_row] = ra.z;
    As[0][a_k + 3][a_row] = ra.w;
    Bs[0][b_k + 0][b_row] = rb.x;
    Bs[0][b_k + 1][b_row] = rb.y;
    Bs[0][b_k + 2][b_row] = rb.z;
    Bs[0][b_k + 3][b_row] = rb.w;
    __syncthreads();

    const int tx = tid & 15;
    const int ty = tid >> 4;

    float acc[8][8];
#pragma unroll
    for (int i = 0; i < 8; ++i)
#pragma unroll
        for (int j = 0; j < 8; ++j) acc[i][j] = 0.0f;

    const int KT = K >> 3;
    int cur = 0;
    for (int kt = 0; kt < KT; ++kt) {
        if (kt + 1 < KT) {
            ra = *(const float4*)(Ap + (long long)(kt + 1) * 8);
            rb = *(const float4*)(Bp + (long long)(kt + 1) * 8);
        }
#pragma unroll
        for (int k = 0; k < 8; ++k) {
            float a[8], b[8];
            *(float4*)&a[0] = *(const float4*)&As[cur][k][ty * 8];
            *(float4*)&a[4] = *(const float4*)&As[cur][k][ty * 8 + 4];
            *(float4*)&b[0] = *(const float4*)&Bs[cur][k][tx * 8];
            *(float4*)&b[4] = *(const float4*)&Bs[cur][k][tx * 8 + 4];
#pragma unroll
            for (int i = 0; i < 8; ++i)
#pragma unroll
                for (int j = 0; j < 8; ++j)
                    acc[i][j] = fmaf(a[i], b[j], acc[i][j]);
        }
        if (kt + 1 < KT) {
            const int nx = cur ^ 1;
            As[nx][a_k + 0][a_row] = ra.x;
            As[nx][a_k + 1][a_row] = ra.y;
            As[nx][a_k + 2][a_row] = ra.z;
            As[nx][a_k + 3][a_row] = ra.w;
            Bs[nx][b_k + 0][b_row] = rb.x;
            Bs[nx][b_k + 1][b_row] = rb.y;
            Bs[nx][b_k + 2][b_row] = rb.z;
            Bs[nx][b_k + 3][b_row] = rb.w;
        }
        __syncthreads();
        cur ^= 1;
    }

    const int scol = bn + tx * 8;
    bool keep[8];
#pragma unroll
    for (int j = 0; j < 8; ++j)
        keep[j] = (mp[(long long)(scol + j) * mStride] != 0);

#pragma unroll
    for (int i = 0; i < 8; ++i) {
        float v[8];
#pragma unroll
        for (int j = 0; j < 8; ++j)
            v[j] = keep[j] ? acc[i][j] : NEGV;
        float* Cp = C + (long long)(bm + ty * 8 + i) * ldc + scol;
        *(float4*)Cp       = make_float4(v[0], v[1], v[2], v[3]);
        *(float4*)(Cp + 4) = make_float4(v[4], v[5], v[6], v[7]);
    }
}

// ---------------------------------------------------------------------------
// In-place row softmax over 2048 elements. One block (256 thr) per row,
// 8 elements per thread, kept fully in registers.
// ---------------------------------------------------------------------------
__global__ __launch_bounds__(256)
void softmax_kernel(float* __restrict__ w)
{
    float* row = w + (long long)blockIdx.x * 2048;
    const int tid = threadIdx.x;

    float4 v0 = *(float4*)(row + tid * 8);
    float4 v1 = *(float4*)(row + tid * 8 + 4);

    float m = fmaxf(fmaxf(fmaxf(v0.x, v0.y), fmaxf(v0.z, v0.w)),
                    fmaxf(fmaxf(v1.x, v1.y), fmaxf(v1.z, v1.w)));
#pragma unroll
    for (int o = 16; o > 0; o >>= 1)
        m = fmaxf(m, __shfl_xor_sync(0xffffffffu, m, o));

    __shared__ float red[8];
    if ((tid & 31) == 0) red[tid >> 5] = m;
    __syncthreads();
    m = fmaxf(fmaxf(fmaxf(red[0], red[1]), fmaxf(red[2], red[3])),
              fmaxf(fmaxf(red[4], red[5]), fmaxf(red[6], red[7])));
    __syncthreads();

    float e[8];
    e[0] = __expf(v0.x - m); e[1] = __expf(v0.y - m);
    e[2] = __expf(v0.z - m); e[3] = __expf(v0.w - m);
    e[4] = __expf(v1.x - m); e[5] = __expf(v1.y - m);
    e[6] = __expf(v1.z - m); e[7] = __expf(v1.w - m);

    float s = ((e[0] + e[1]) + (e[2] + e[3])) + ((e[4] + e[5]) + (e[6] + e[7]));
#pragma unroll
    for (int o = 16; o > 0; o >>= 1)
        s += __shfl_xor_sync(0xffffffffu, s, o);
    if ((tid & 31) == 0) red[tid >> 5] = s;
    __syncthreads();
    s = ((red[0] + red[1]) + (red[2] + red[3])) + ((red[4] + red[5]) + (red[6] + red[7]));

    const float inv = 1.0f / s;
    *(float4*)(row + tid * 8)     = make_float4(e[0] * inv, e[1] * inv, e[2] * inv, e[3] * inv);
    *(float4*)(row + tid * 8 + 4) = make_float4(e[4] * inv, e[5] * inv, e[6] * inv, e[7] * inv);
}

// ---------------------------------------------------------------------------
// Launch. Layouts:
//   enc  [s][b][e]  (2048,32,256)   dec [d][b][h] (512,32,256)
//   W    [h][e]     (256,256)       mask[s][b]    (2048,32) int32
//   out  = attention_vector (512,32,256) ++ weights ((32*512),2048)
// proj scratch layout: proj[(d*32+b)*256 + e]  (== dec row layout)
// ---------------------------------------------------------------------------
extern "C" void kernel_launch(void* const* d_in, const int* in_sizes, int n_in,
                              void* d_out, int out_size)
{
    const float* enc = (const float*)d_in[0];
    const float* dec = (const float*)d_in[1];
    const float* Wg  = (const float*)d_in[2];
    const int*   mk  = (const int*)d_in[3];
    float* out = (float*)d_out;

    const long long AV = 512LL * 32 * 256;       // 4,194,304
    const long long WT = 16384LL * 2048;         // 33,554,432

    void* p;
    cudaGetSymbolAddress(&p, g_proj);
    float* proj = (float*)p;
    cudaGetSymbolAddress(&p, g_scores);
    float* scratch = (float*)p;

    float* av = out;
    float* wt = ((long long)out_size >= AV + WT) ? (out + AV) : scratch;

    dim3 blk(256);

    // K1: proj = dec @ W            M=16384 (rows d*32+b), N=256, K=256
    gemm_nn_kernel<<<dim3(2, 128, 1), blk>>>(
        dec, 0, 256,
        Wg,  0, 256,
        proj, 0, 256,
        256);

    // K2: scores[b,d,s] = proj[b,d,:] . enc[b,s,:], masked   (per-batch NT)
    gemm_nt_mask_kernel<<<dim3(16, 4, 32), blk>>>(
        proj, 256, 8192,
        enc,  256, 8192,
        wt, 512LL * 2048, 2048,
        mk, 32,
        256);

    // K3: softmax over each of the 16384 rows (in place)
    softmax_kernel<<<16384, blk>>>(wt);

    // K4: attn[b,d,e] = weights[b,d,:] @ enc[b,:,e]          (per-batch NN)
    gemm_nn_kernel<<<dim3(2, 4, 32), blk>>>(
        wt, 512LL * 2048, 2048,
        enc, 256, 8192,
        av, 256, 8192,
        2048);
}

// round 17
// speedup vs baseline: 1.1352x; 1.1352x over previous
#include <cuda_runtime.h>

#define NEGV (-1.0e12f)

// Scratch (allocation-free rule: __device__ globals)
__device__ float g_proj[512u * 32u * 256u];          // 16 MB: proj[(d*32+b)*256 + e]
__device__ float g_scores[16384ull * 2048ull];       // 134 MB fallback if out lacks weights

// ---------------------------------------------------------------------------
// Generic NN GEMM: C[m,n] = sum_k A[m*lda+k] * B[k*ldb+n], 128x128 tile, BK=8,
// 256 threads, double-buffered smem. Per-thread tile: split 4+4 rows/cols
// (rows ty*4+{0..3,64..67}, cols tx*4+{0..3,64..67}) so fragment LDS.128 are
// stride-16B => conflict-free (the old 8x8 mapping had 2-way conflicts).
// ---------------------------------------------------------------------------
__global__ __launch_bounds__(256, 2)
void gemm_nn_kernel(const float* __restrict__ A, long long sAz, int lda,
                    const float* __restrict__ B, long long sBz, int ldb,
                    float* __restrict__ C, long long sCz, int ldc,
                    int K)
{
    A += (long long)blockIdx.z * sAz;
    B += (long long)blockIdx.z * sBz;
    C += (long long)blockIdx.z * sCz;
    const int bm = blockIdx.y * 128;
    const int bn = blockIdx.x * 128;

    __shared__ float As[2][8][128];
    __shared__ float Bs[2][8][128];

    const int tid = threadIdx.x;
    const int a_row = tid >> 1;          // 0..127
    const int a_k   = (tid & 1) * 4;     // 0 or 4
    const int b_k   = tid >> 5;          // 0..7
    const int b_n   = (tid & 31) * 4;    // 0..124

    const float* Ap = A + (long long)(bm + a_row) * lda + a_k;
    const float* Bp = B + (long long)b_k * ldb + bn + b_n;

    float4 ra = *(const float4*)Ap;
    float4 rb = *(const float4*)Bp;
    As[0][a_k + 0][a_row] = ra.x;
    As[0][a_k + 1][a_row] = ra.y;
    As[0][a_k + 2][a_row] = ra.z;
    As[0][a_k + 3][a_row] = ra.w;
    *(float4*)&Bs[0][b_k][b_n] = rb;
    __syncthreads();

    const int tx = tid & 15;
    const int ty = tid >> 4;
    const int row0 = ty * 4;             // + {0..3} and +64
    const int col0 = tx * 4;             // + {0..3} and +64

    float acc[8][8];
#pragma unroll
    for (int i = 0; i < 8; ++i)
#pragma unroll
        for (int j = 0; j < 8; ++j) acc[i][j] = 0.0f;

    const int KT = K >> 3;
    int cur = 0;
    for (int kt = 0; kt < KT; ++kt) {
        if (kt + 1 < KT) {
            ra = *(const float4*)(Ap + (long long)(kt + 1) * 8);
            rb = *(const float4*)(Bp + (long long)(kt + 1) * 8 * ldb);
        }
#pragma unroll
        for (int k = 0; k < 8; ++k) {
            float a[8], b[8];
            *(float4*)&a[0] = *(const float4*)&As[cur][k][row0];
            *(float4*)&a[4] = *(const float4*)&As[cur][k][row0 + 64];
            *(float4*)&b[0] = *(const float4*)&Bs[cur][k][col0];
            *(float4*)&b[4] = *(const float4*)&Bs[cur][k][col0 + 64];
#pragma unroll
            for (int i = 0; i < 8; ++i)
#pragma unroll
                for (int j = 0; j < 8; ++j)
                    acc[i][j] = fmaf(a[i], b[j], acc[i][j]);
        }
        if (kt + 1 < KT) {
            const int nx = cur ^ 1;
            As[nx][a_k + 0][a_row] = ra.x;
            As[nx][a_k + 1][a_row] = ra.y;
            As[nx][a_k + 2][a_row] = ra.z;
            As[nx][a_k + 3][a_row] = ra.w;
            *(float4*)&Bs[nx][b_k][b_n] = rb;
        }
        __syncthreads();
        cur ^= 1;
    }

#pragma unroll
    for (int ih = 0; ih < 2; ++ih)
#pragma unroll
        for (int i = 0; i < 4; ++i) {
            const int ai = ih * 4 + i;
            float* Cp = C + (long long)(bm + row0 + ih * 64 + i) * ldc + bn;
            *(float4*)(Cp + col0)      = make_float4(acc[ai][0], acc[ai][1], acc[ai][2], acc[ai][3]);
            *(float4*)(Cp + col0 + 64) = make_float4(acc[ai][4], acc[ai][5], acc[ai][6], acc[ai][7]);
        }
}

// ---------------------------------------------------------------------------
// NT GEMM with mask epilogue: C[m,n] = sum_k A[m*lda+k] * B[n*ldb+k]
// Mask: element for column n is Mk[blockIdx.z + n*mStride]; 0 -> NEGV.
// Same split 4+4 conflict-free fragment mapping.
// ---------------------------------------------------------------------------
__global__ __launch_bounds__(256, 2)
void gemm_nt_mask_kernel(const float* __restrict__ A, long long sAz, int lda,
                         const float* __restrict__ B, long long sBz, int ldb,
                         float* __restrict__ C, long long sCz, int ldc,
                         const int* __restrict__ Mk, int mStride,
                         int K)
{
    A += (long long)blockIdx.z * sAz;
    B += (long long)blockIdx.z * sBz;
    C += (long long)blockIdx.z * sCz;
    const int* mp = Mk + blockIdx.z;
    const int bm = blockIdx.y * 128;
    const int bn = blockIdx.x * 128;

    __shared__ float As[2][8][128];
    __shared__ float Bs[2][8][128];

    const int tid = threadIdx.x;
    const int a_row = tid >> 1;
    const int a_k   = (tid & 1) * 4;
    const int b_row = tid >> 1;
    const int b_k   = (tid & 1) * 4;

    const float* Ap = A + (long long)(bm + a_row) * lda + a_k;
    const float* Bp = B + (long long)(bn + b_row) * ldb + b_k;

    float4 ra = *(const float4*)Ap;
    float4 rb = *(const float4*)Bp;
    As[0][a_k + 0][a_row] = ra.x;
    As[0][a_k + 1][a_row] = ra.y;
    As[0][a_k + 2][a_row] = ra.z;
    As[0][a_k + 3][a_row] = ra.w;
    Bs[0][b_k + 0][b_row] = rb.x;
    Bs[0][b_k + 1][b_row] = rb.y;
    Bs[0][b_k + 2][b_row] = rb.z;
    Bs[0][b_k + 3][b_row] = rb.w;
    __syncthreads();

    const int tx = tid & 15;
    const int ty = tid >> 4;
    const int row0 = ty * 4;
    const int col0 = tx * 4;

    float acc[8][8];
#pragma unroll
    for (int i = 0; i < 8; ++i)
#pragma unroll
        for (int j = 0; j < 8; ++j) acc[i][j] = 0.0f;

    const int KT = K >> 3;
    int cur = 0;
    for (int kt = 0; kt < KT; ++kt) {
        if (kt + 1 < KT) {
            ra = *(const float4*)(Ap + (long long)(kt + 1) * 8);
            rb = *(const float4*)(Bp + (long long)(kt + 1) * 8);
        }
#pragma unroll
        for (int k = 0; k < 8; ++k) {
            float a[8], b[8];
            *(float4*)&a[0] = *(const float4*)&As[cur][k][row0];
            *(float4*)&a[4] = *(const float4*)&As[cur][k][row0 + 64];
            *(float4*)&b[0] = *(const float4*)&Bs[cur][k][col0];
            *(float4*)&b[4] = *(const float4*)&Bs[cur][k][col0 + 64];
#pragma unroll
            for (int i = 0; i < 8; ++i)
#pragma unroll
                for (int j = 0; j < 8; ++j)
                    acc[i][j] = fmaf(a[i], b[j], acc[i][j]);
        }
        if (kt + 1 < KT) {
            const int nx = cur ^ 1;
            As[nx][a_k + 0][a_row] = ra.x;
            As[nx][a_k + 1][a_row] = ra.y;
            As[nx][a_k + 2][a_row] = ra.z;
            As[nx][a_k + 3][a_row] = ra.w;
            Bs[nx][b_k + 0][b_row] = rb.x;
            Bs[nx][b_k + 1][b_row] = rb.y;
            Bs[nx][b_k + 2][b_row] = rb.z;
            Bs[nx][b_k + 3][b_row] = rb.w;
        }
        __syncthreads();
        cur ^= 1;
    }

    // Mask for the 8 columns this thread owns: col0+{0..3}, col0+64+{0..3}
    bool keep[8];
#pragma unroll
    for (int j = 0; j < 8; ++j) {
        const int scol = bn + col0 + ((j < 4) ? j : 64 + (j - 4));
        keep[j] = (mp[(long long)scol * mStride] != 0);
    }

#pragma unroll
    for (int ih = 0; ih < 2; ++ih)
#pragma unroll
        for (int i = 0; i < 4; ++i) {
            const int ai = ih * 4 + i;
            float v[8];
#pragma unroll
            for (int j = 0; j < 8; ++j)
                v[j] = keep[j] ? acc[ai][j] : NEGV;
            float* Cp = C + (long long)(bm + row0 + ih * 64 + i) * ldc + bn;
            *(float4*)(Cp + col0)      = make_float4(v[0], v[1], v[2], v[3]);
            *(float4*)(Cp + col0 + 64) = make_float4(v[4], v[5], v[6], v[7]);
        }
}

// ---------------------------------------------------------------------------
// In-place row softmax over 2048 elements. One block (256 thr) per row,
// 8 elements per thread, kept fully in registers.
// ---------------------------------------------------------------------------
__global__ __launch_bounds__(256)
void softmax_kernel(float* __restrict__ w)
{
    float* row = w + (long long)blockIdx.x * 2048;
    const int tid = threadIdx.x;

    float4 v0 = *(float4*)(row + tid * 8);
    float4 v1 = *(float4*)(row + tid * 8 + 4);

    float m = fmaxf(fmaxf(fmaxf(v0.x, v0.y), fmaxf(v0.z, v0.w)),
                    fmaxf(fmaxf(v1.x, v1.y), fmaxf(v1.z, v1.w)));
#pragma unroll
    for (int o = 16; o > 0; o >>= 1)
        m = fmaxf(m, __shfl_xor_sync(0xffffffffu, m, o));

    __shared__ float red[8];
    if ((tid & 31) == 0) red[tid >> 5] = m;
    __syncthreads();
    m = fmaxf(fmaxf(fmaxf(red[0], red[1]), fmaxf(red[2], red[3])),
              fmaxf(fmaxf(red[4], red[5]), fmaxf(red[6], red[7])));
    __syncthreads();

    float e[8];
    e[0] = __expf(v0.x - m); e[1] = __expf(v0.y - m);
    e[2] = __expf(v0.z - m); e[3] = __expf(v0.w - m);
    e[4] = __expf(v1.x - m); e[5] = __expf(v1.y - m);
    e[6] = __expf(v1.z - m); e[7] = __expf(v1.w - m);

    float s = ((e[0] + e[1]) + (e[2] + e[3])) + ((e[4] + e[5]) + (e[6] + e[7]));
#pragma unroll
    for (int o = 16; o > 0; o >>= 1)
        s += __shfl_xor_sync(0xffffffffu, s, o);
    if ((tid & 31) == 0) red[tid >> 5] = s;
    __syncthreads();
    s = ((red[0] + red[1]) + (red[2] + red[3])) + ((red[4] + red[5]) + (red[6] + red[7]));

    const float inv = 1.0f / s;
    *(float4*)(row + tid * 8)     = make_float4(e[0] * inv, e[1] * inv, e[2] * inv, e[3] * inv);
    *(float4*)(row + tid * 8 + 4) = make_float4(e[4] * inv, e[5] * inv, e[6] * inv, e[7] * inv);
}

// ---------------------------------------------------------------------------
// Launch. Layouts:
//   enc  [s][b][e]  (2048,32,256)   dec [d][b][h] (512,32,256)
//   W    [h][e]     (256,256)       mask[s][b]    (2048,32) int32
//   out  = attention_vector (512,32,256) ++ weights ((32*512),2048)
// proj scratch layout: proj[(d*32+b)*256 + e]  (== dec row layout)
// ---------------------------------------------------------------------------
extern "C" void kernel_launch(void* const* d_in, const int* in_sizes, int n_in,
                              void* d_out, int out_size)
{
    const float* enc = (const float*)d_in[0];
    const float* dec = (const float*)d_in[1];
    const float* Wg  = (const float*)d_in[2];
    const int*   mk  = (const int*)d_in[3];
    float* out = (float*)d_out;

    const long long AV = 512LL * 32 * 256;       // 4,194,304
    const long long WT = 16384LL * 2048;         // 33,554,432

    void* p;
    cudaGetSymbolAddress(&p, g_proj);
    float* proj = (float*)p;
    cudaGetSymbolAddress(&p, g_scores);
    float* scratch = (float*)p;

    float* av = out;
    float* wt = ((long long)out_size >= AV + WT) ? (out + AV) : scratch;

    dim3 blk(256);

    // K1: proj = dec @ W            M=16384 (rows d*32+b), N=256, K=256
    gemm_nn_kernel<<<dim3(2, 128, 1), blk>>>(
        dec, 0, 256,
        Wg,  0, 256,
        proj, 0, 256,
        256);

    // K2: scores[b,d,s] = proj[b,d,:] . enc[b,s,:], masked   (per-batch NT)
    gemm_nt_mask_kernel<<<dim3(16, 4, 32), blk>>>(
        proj, 256, 8192,
        enc,  256, 8192,
        wt, 512LL * 2048, 2048,
        mk, 32,
        256);

    // K3: softmax over each of the 16384 rows (in place)
    softmax_kernel<<<16384, blk>>>(wt);

    // K4: attn[b,d,e] = weights[b,d,:] @ enc[b,:,e]          (per-batch NN)
    gemm_nn_kernel<<<dim3(2, 4, 32), blk>>>(
        wt, 512LL * 2048, 2048,
        enc, 256, 8192,
        av, 256, 8192,
        2048);
}